// round 12
// baseline (speedup 1.0000x reference)
#include <cuda_runtime.h>
#include <cstdint>

#define NUM_SEGMENTS 512
#define THREADS 512
#define ROWG (THREADS / 16)   // 32 row-groups, 16 float4 lanes per 64-float row
#define NUNITS (2 * NUM_SEGMENTS)

// Disjoint per-unit partial slots (written, not accumulated -> no zeroing needed)
__device__ float    g_psum[NUNITS * 64];
__device__ float    g_pssq[NUNITS];
__device__ unsigned g_flag[NUNITS];   // zeroed by init kernel each launch

__device__ __forceinline__ int lower_bound_i32(const int* __restrict__ b, int n, int v) {
    int lo = 0, hi = n;
    while (lo < hi) {
        int mid = (lo + hi) >> 1;
        if (b[mid] < v) lo = mid + 1; else hi = mid;
    }
    return lo;
}

__device__ __forceinline__ unsigned ld_acquire_u32(const unsigned* p) {
    unsigned v;
    asm volatile("ld.acquire.gpu.global.u32 %0, [%1];" : "=r"(v) : "l"(p));
    return v;
}
__device__ __forceinline__ void st_release_u32(unsigned* p, unsigned v) {
    asm volatile("st.release.gpu.global.u32 [%0], %1;" :: "l"(p), "r"(v) : "memory");
}

__global__ void init_flags_kernel() {
    if (threadIdx.x < NUNITS) g_flag[blockIdx.x * 1024 + threadIdx.x] = 0u;
}

extern __shared__ char smem_pad[];   // 96 KB requested: enforce 2 CTA/SM (regs=64 also caps it)

__global__ __launch_bounds__(THREADS, 2)
void pairnorm_kernel(const float4* __restrict__ x4,
                     const int* __restrict__ batch,   // int32 (JAX x64 disabled)
                     float4* __restrict__ out4,
                     int N)
{
    __shared__ float4 s_red[ROWG * 16];        // 8 KB tree-reduce scratch
    __shared__ float  s_warp[THREADS / 32];
    __shared__ float  s_mean[64];
    __shared__ float  s_ssq2[2];               // [0]=own total ssq, [1]=peer ssq
    __shared__ float  s_inv;
    __shared__ int    s_lo, s_hi;

    const int tid  = threadIdx.x;
    const int unit = (int)blockIdx.x;
    const int seg  = unit >> 1;
    const int rank = unit & 1;
    const int peer = unit ^ 1;

    if (tid == 0)  s_lo = lower_bound_i32(batch, N, seg);
    if (tid == 32) s_hi = lower_bound_i32(batch, N, seg + 1);
    __syncthreads();
    const int lo = s_lo, hi = s_hi;
    const int cnt = hi - lo;
    const int h0 = (cnt + 1) >> 1;
    const int mylo = rank ? (lo + h0) : lo;
    const int myhi = rank ? hi        : (lo + h0);

    const int lane16 = tid & 15;
    const int rg     = tid >> 4;

    // ---- Pass 1: this CTA's half-segment: sum[64] + sum of squared norms ----
    float4 acc = make_float4(0.f, 0.f, 0.f, 0.f);
    float ssq = 0.f;
    #pragma unroll 8
    for (int r = mylo + rg; r < myhi; r += ROWG) {
        float4 v = x4[(size_t)r * 16 + lane16];
        acc.x += v.x; acc.y += v.y; acc.z += v.z; acc.w += v.w;
        ssq += v.x * v.x + v.y * v.y + v.z * v.z + v.w * v.w;
    }
    s_red[rg * 16 + lane16] = acc;

    #pragma unroll
    for (int off = 16; off > 0; off >>= 1)
        ssq += __shfl_xor_sync(0xffffffffu, ssq, off);
    if ((tid & 31) == 0) s_warp[tid >> 5] = ssq;
    __syncthreads();

    #pragma unroll
    for (int off = ROWG / 2; off >= 1; off >>= 1) {
        if (rg < off) {
            float4 a = s_red[rg * 16 + lane16];
            float4 b = s_red[(rg + off) * 16 + lane16];
            a.x += b.x; a.y += b.y; a.z += b.z; a.w += b.w;
            s_red[rg * 16 + lane16] = a;
        }
        __syncthreads();
    }

    // publish this unit's partials to its disjoint global slot
    if (tid < 64) {
        g_psum[unit * 64 + tid] = ((const float*)s_red)[tid];
    } else if (tid == 64) {
        float t = 0.f;
        #pragma unroll
        for (int w = 0; w < THREADS / 32; w++) t += s_warp[w];
        s_ssq2[0] = t;
        g_pssq[unit] = t;
    }
    __syncthreads();

    if (tid == 0) {
        __threadfence();                      // partials visible GPU-wide
        st_release_u32(&g_flag[unit], 1u);    // signal peer
        // spin for peer's partials (peers are adjacent bids -> co-resident)
        while (ld_acquire_u32(&g_flag[peer]) == 0u) __nanosleep(64);
    }
    __syncthreads();

    // combine own (smem) + peer (global, L2-hot) partials
    if (tid < 64) {
        s_mean[tid] = ((const float*)s_red)[tid] + g_psum[peer * 64 + tid];
    } else if (tid == 64) {
        s_ssq2[1] = g_pssq[peer];
    }
    __syncthreads();

    // finalize: mean and 1/sqrt(mean centered sq-norm)
    if (tid == 0) {
        const float invc = 1.f / (float)(cnt > 0 ? cnt : 1);
        float msq = 0.f;
        #pragma unroll
        for (int i = 0; i < 64; i++) {
            float m = s_mean[i] * invc;
            s_mean[i] = m;
            msq += m * m;
        }
        // sum||x-m||^2 / cnt = sumsq/cnt - ||m||^2
        float var = fmaxf((s_ssq2[0] + s_ssq2[1]) * invc - msq, 0.f);
        s_inv = rsqrtf(var);
    }
    __syncthreads();

    const float4 mean = ((const float4*)s_mean)[lane16];
    const float inv = s_inv;

    // ---- Pass 2: re-read own half (L2-hot, evict-first) and stream out ----
    #pragma unroll 8
    for (int r = mylo + rg; r < myhi; r += ROWG) {
        float4 v = __ldcs(&x4[(size_t)r * 16 + lane16]);   // last use: evict-first
        float4 o;
        o.x = (v.x - mean.x) * inv;
        o.y = (v.y - mean.y) * inv;
        o.z = (v.z - mean.z) * inv;
        o.w = (v.w - mean.w) * inv;
        __stcs(&out4[(size_t)r * 16 + lane16], o);         // streaming store
    }
}

extern "C" void kernel_launch(void* const* d_in, const int* in_sizes, int n_in,
                              void* d_out, int out_size)
{
    const float4* x4    = (const float4*)d_in[0];
    const int*    batch = (const int*)d_in[1];
    float4*       out4  = (float4*)d_out;
    const int N = in_sizes[1];   // 1,000,000 rows; D = 64 fixed

    init_flags_kernel<<<1, 1024>>>();

    // 96 KB dynamic smem: 3 CTAs would exceed the 227 KB cap -> 2 CTA/SM
    // (registers already enforce this at 64 regs x 512 thr). Concurrent
    // resident units ~296 -> ~148 segments x ~500 KB = 74 MB in L2.
    static const int kSmem = 96 * 1024;
    cudaFuncSetAttribute(pairnorm_kernel, cudaFuncAttributeMaxDynamicSharedMemorySize, kSmem);
    pairnorm_kernel<<<NUNITS, THREADS, kSmem>>>(x4, batch, out4, N);
}

// round 14
// speedup vs baseline: 1.0981x; 1.0981x over previous
#include <cuda_runtime.h>

#define NUM_SEGMENTS 512
#define NCTAS 128
#define SEGS_PER_CTA (NUM_SEGMENTS / NCTAS)   // 4
#define THREADS 1024
#define ROWG (THREADS / 16)                   // 64 row-groups, 16 float4 lanes per 64-float row

__device__ __forceinline__ int lower_bound_i32(const int* __restrict__ b, int n, int v) {
    int lo = 0, hi = n;
    while (lo < hi) {
        int mid = (lo + hi) >> 1;
        if (b[mid] < v) lo = mid + 1; else hi = mid;
    }
    return lo;
}

extern __shared__ char smem_pad[];   // 128 KB requested -> guarantees 1 CTA/SM

__global__ __launch_bounds__(THREADS, 1)
void pairnorm_kernel(const float4* __restrict__ x4,
                     const int* __restrict__ batch,   // int32 (JAX x64 disabled)
                     float4* __restrict__ out4,
                     int N)
{
    __shared__ float4 s_red[ROWG * 16];          // 16 KB tree-reduce scratch (reused per segment)
    __shared__ float  s_warp[THREADS / 32];
    __shared__ float4 s_mean[16];                // finalized mean (separate from s_red: race-free overlap)
    __shared__ float  s_inv;
    __shared__ int    s_bound[SEGS_PER_CTA + 1];

    const int tid  = threadIdx.x;
    const int seg0 = (int)blockIdx.x * SEGS_PER_CTA;

    // all segment boundaries up front -> no per-segment boundary barrier
    if (tid <= SEGS_PER_CTA)
        s_bound[tid] = lower_bound_i32(batch, N, seg0 + tid);
    __syncthreads();

    const int lane16 = tid & 15;
    const int rg     = tid >> 4;

    for (int si = 0; si < SEGS_PER_CTA; si++) {
        const int lo = s_bound[si];
        const int hi = s_bound[si + 1];

        // ---- Pass 1: sum[64] + sum of squared norms ----
        float4 acc = make_float4(0.f, 0.f, 0.f, 0.f);
        float ssq = 0.f;
        #pragma unroll 8
        for (int r = lo + rg; r < hi; r += ROWG) {
            float4 v = x4[(size_t)r * 16 + lane16];
            acc.x += v.x; acc.y += v.y; acc.z += v.z; acc.w += v.w;
            ssq += v.x * v.x + v.y * v.y + v.z * v.z + v.w * v.w;
        }
        s_red[rg * 16 + lane16] = acc;

        #pragma unroll
        for (int off = 16; off > 0; off >>= 1)
            ssq += __shfl_xor_sync(0xffffffffu, ssq, off);
        if ((tid & 31) == 0) s_warp[tid >> 5] = ssq;
        __syncthreads();

        // tree-reduce 64 row-group partials down to row 0
        #pragma unroll
        for (int off = ROWG / 2; off >= 1; off >>= 1) {
            if (rg < off) {
                float4 a = s_red[rg * 16 + lane16];
                float4 b = s_red[(rg + off) * 16 + lane16];
                a.x += b.x; a.y += b.y; a.z += b.z; a.w += b.w;
                s_red[rg * 16 + lane16] = a;
            }
            __syncthreads();
        }

        // finalize: mean + 1/sqrt(mean centered sq-norm)
        if (tid == 0) {
            float tot = 0.f;
            #pragma unroll
            for (int w = 0; w < THREADS / 32; w++) tot += s_warp[w];
            const int cnt = hi - lo;
            const float invc = 1.f / (float)(cnt > 0 ? cnt : 1);
            float msq = 0.f;
            #pragma unroll
            for (int i = 0; i < 16; i++) {
                float4 m = s_red[i];
                m.x *= invc; m.y *= invc; m.z *= invc; m.w *= invc;
                s_mean[i] = m;
                msq += m.x * m.x + m.y * m.y + m.z * m.z + m.w * m.w;
            }
            // sum||x-m||^2 / cnt = sumsq/cnt - ||m||^2
            float var = fmaxf(tot * invc - msq, 0.f);
            s_inv = rsqrtf(var);
        }
        __syncthreads();

        const float4 mean = s_mean[lane16];
        const float inv = s_inv;

        // ---- Pass 2: re-read (L2-hot, evict-first) and write out ----
        // No trailing barrier: fast warps flow into pass-1 of the next
        // segment (register-only until the s_red store, which is followed
        // by a barrier) while stragglers finish stores here.
        #pragma unroll 8
        for (int r = lo + rg; r < hi; r += ROWG) {
            float4 v = __ldcs(&x4[(size_t)r * 16 + lane16]);
            float4 o;
            o.x = (v.x - mean.x) * inv;
            o.y = (v.y - mean.y) * inv;
            o.z = (v.z - mean.z) * inv;
            o.w = (v.w - mean.w) * inv;
            out4[(size_t)r * 16 + lane16] = o;
        }
    }
}

extern "C" void kernel_launch(void* const* d_in, const int* in_sizes, int n_in,
                              void* d_out, int out_size)
{
    const float4* x4    = (const float4*)d_in[0];
    const int*    batch = (const int*)d_in[1];
    float4*       out4  = (float4*)d_out;
    const int N = in_sizes[1];   // 1,000,000 rows; D = 64 fixed

    // 128 KB dynamic smem (+16.5 KB static): two CTAs would exceed the
    // 227 KB/SM cap -> exactly 1 CTA/SM. 128 persistent CTAs, each owning
    // 4 whole segments -> no wave quantization, no cross-CTA sync, and the
    // concurrent pass-1 working set (128 x ~500 KB = 64 MB) stays in L2
    // for the pass-2 re-read.
    static const int kSmem = 128 * 1024;
    cudaFuncSetAttribute(pairnorm_kernel, cudaFuncAttributeMaxDynamicSharedMemorySize, kSmem);
    pairnorm_kernel<<<NCTAS, THREADS, kSmem>>>(x4, batch, out4, N);
}